// round 3
// baseline (speedup 1.0000x reference)
#include <cuda_runtime.h>

// Problem constants (fixed shapes for this problem instance)
#define NC 100     // num classes
#define NP 64      // features per row

// Global scratch (device globals: allocation-free, graph-capture safe)
__device__ float        g_s[NC * NP];   // per-(class,feature) sums
__device__ float        g_rss[NC];      // per-class sum of ||x_i||^2
__device__ unsigned int g_cnt[NC];      // per-class counts

// ---------------------------------------------------------------------------
// Kernel 1: zero the global accumulators (must run every replay)
// ---------------------------------------------------------------------------
__global__ void CLIR_zero_kernel() {
    int i = blockIdx.x * blockDim.x + threadIdx.x;
    if (i < NC * NP) g_s[i] = 0.0f;
    if (i < NC) { g_rss[i] = 0.0f; g_cnt[i] = 0u; }
}

// ---------------------------------------------------------------------------
// Kernel 2: accumulate. Half-warp-per-row, shared-memory privatization.
//   - 16 lanes x float4 = 64 floats = one full row; warp covers 2 rows/iter
//   - 4 shared f32 atomics per lane for s (64 per row)
//   - ||x||^2 reduced over the 16-lane group (4 shfls), 1 atomic per row
// ---------------------------------------------------------------------------
__global__ void __launch_bounds__(512, 2)
CLIR_accum_kernel(const float* __restrict__ x,
                  const int* __restrict__ t,   // labels are int32 (harness converts int64)
                  int n) {
    __shared__ float        s_s[NC * NP];   // 25.6 KB
    __shared__ float        s_rss[NC];
    __shared__ unsigned int s_cnt[NC];

    for (int j = threadIdx.x; j < NC * NP; j += blockDim.x) s_s[j] = 0.0f;
    for (int j = threadIdx.x; j < NC; j += blockDim.x) { s_rss[j] = 0.0f; s_cnt[j] = 0u; }
    __syncthreads();

    const int lane  = threadIdx.x & 31;
    const int half  = lane >> 4;           // 0 or 1: which row of the pair
    const int l16   = lane & 15;           // position within the row
    const int gw    = (blockIdx.x * blockDim.x + threadIdx.x) >> 5;
    const int nw    = (gridDim.x * blockDim.x) >> 5;
    const float4* __restrict__ x4 = (const float4*)x;

    // pairs of rows: warp gw handles rows {2k, 2k+1}
    const int npairs = n >> 1;
    for (int k = gw; k < npairs; k += nw) {
        int row = (k << 1) + half;
        float4 v = __ldg(&x4[(long long)row * 16 + l16]);
        int c = __ldg(&t[row]);            // broadcast within each 16-lane group

        int base = c * NP + l16 * 4;
        atomicAdd(&s_s[base + 0], v.x);
        atomicAdd(&s_s[base + 1], v.y);
        atomicAdd(&s_s[base + 2], v.z);
        atomicAdd(&s_s[base + 3], v.w);

        // per-row squared norm, reduced over the 16-lane group
        float q = v.x * v.x + v.y * v.y + v.z * v.z + v.w * v.w;
        q += __shfl_xor_sync(0xffffffffu, q, 8);
        q += __shfl_xor_sync(0xffffffffu, q, 4);
        q += __shfl_xor_sync(0xffffffffu, q, 2);
        q += __shfl_xor_sync(0xffffffffu, q, 1);
        if (l16 == 0) {
            atomicAdd(&s_rss[c], q);
            atomicAdd(&s_cnt[c], 1u);
        }
    }

    // odd tail row (n odd): first warp, half 0 handles it
    if ((n & 1) && gw == 0 && half == 0) {
        int row = n - 1;
        float4 v = __ldg(&x4[(long long)row * 16 + l16]);
        int c = __ldg(&t[row]);
        int base = c * NP + l16 * 4;
        atomicAdd(&s_s[base + 0], v.x);
        atomicAdd(&s_s[base + 1], v.y);
        atomicAdd(&s_s[base + 2], v.z);
        atomicAdd(&s_s[base + 3], v.w);
        float q = v.x * v.x + v.y * v.y + v.z * v.z + v.w * v.w;
        q += __shfl_xor_sync(0x0000ffffu, q, 8);
        q += __shfl_xor_sync(0x0000ffffu, q, 4);
        q += __shfl_xor_sync(0x0000ffffu, q, 2);
        q += __shfl_xor_sync(0x0000ffffu, q, 1);
        if (l16 == 0) {
            atomicAdd(&s_rss[c], q);
            atomicAdd(&s_cnt[c], 1u);
        }
    }
    __syncthreads();

    // Flush block-private accumulators to global
    for (int j = threadIdx.x; j < NC * NP; j += blockDim.x) {
        float v = s_s[j];
        if (v != 0.0f) atomicAdd(&g_s[j], v);
    }
    for (int j = threadIdx.x; j < NC; j += blockDim.x) {
        float r = s_rss[j];
        if (r != 0.0f) atomicAdd(&g_rss[j], r);
        unsigned cgt = s_cnt[j];
        if (cgt) atomicAdd(&g_cnt[j], cgt);
    }
}

// ---------------------------------------------------------------------------
// Kernel 3: finalize.
//   result = (1/NC) * sum_c [ (rowSS_c - sum_p s_cp^2 / n_c) / (n_c - 1) ]
// ---------------------------------------------------------------------------
__global__ void CLIR_final_kernel(float* __restrict__ out) {
    __shared__ float red[256];
    float acc = 0.0f;

    // -sum_{c,p} s^2 / (n_c * (n_c - 1))
    for (int j = threadIdx.x; j < NC * NP; j += blockDim.x) {
        int c = j >> 6;
        float ncf = (float)g_cnt[c];
        float s = g_s[j];
        acc -= (s * s) / (ncf * (ncf - 1.0f));
    }
    // +sum_c rowSS_c / (n_c - 1)
    for (int c = threadIdx.x; c < NC; c += blockDim.x) {
        float ncf = (float)g_cnt[c];
        acc += g_rss[c] / (ncf - 1.0f);
    }

    red[threadIdx.x] = acc;
    __syncthreads();
    for (int off = 128; off > 0; off >>= 1) {
        if (threadIdx.x < off) red[threadIdx.x] += red[threadIdx.x + off];
        __syncthreads();
    }
    if (threadIdx.x == 0) out[0] = red[0] / (float)NC;
}

// ---------------------------------------------------------------------------
// Launch
// ---------------------------------------------------------------------------
extern "C" void kernel_launch(void* const* d_in, const int* in_sizes, int n_in,
                              void* d_out, int out_size) {
    const float* x = (const float*)d_in[0];
    const int*   t = (const int*)d_in[1];
    int n = in_sizes[1];           // number of rows (element count of t)

    float* out = (float*)d_out;

    CLIR_zero_kernel<<<7, 1024>>>();
    CLIR_accum_kernel<<<296, 512>>>(x, t, n);
    CLIR_final_kernel<<<1, 256>>>(out);
}

// round 5
// speedup vs baseline: 1.8045x; 1.8045x over previous
#include <cuda_runtime.h>

#define NC 100     // num classes
#define NP 64      // features per row

// Global scratch (device globals: allocation-free, graph-capture safe)
__device__ float        g_s[NC * NP];     // per-(class,feature) sums
__device__ float        g_q[NC * 32];     // per-class, per-lane partial sums of squares
__device__ unsigned int g_cnt[NC];        // per-class counts

// ---------------------------------------------------------------------------
// Kernel 1: zero the global accumulators (runs every replay)
// ---------------------------------------------------------------------------
__global__ void CLIR_zero_kernel() {
    int i = blockIdx.x * blockDim.x + threadIdx.x;
    if (i < NC * NP) g_s[i] = 0.0f;
    if (i < NC * 32) g_q[i] = 0.0f;
    if (i < NC) g_cnt[i] = 0u;
}

// ---------------------------------------------------------------------------
// Kernel 2: accumulate. Warp-per-row, conflict-free lane-owned banks.
//   lane l owns features {l, l+32}:  (c*64+l) % 32 == l  and
//   (c*64+l+32) % 32 == l  -> every shared atomic from lane l hits bank l.
//   sum-of-squares: lane l adds a^2+b^2 into s_q[c*32+l] (bank l) — no shfl
//   chain, no divergent atomic. 2-row unroll for load MLP.
// ---------------------------------------------------------------------------
__global__ void __launch_bounds__(512, 3)
CLIR_accum_kernel(const float* __restrict__ x,
                  const int* __restrict__ t,
                  int n) {
    __shared__ float        s_s[NC * NP];   // 25.6 KB
    __shared__ float        s_q[NC * 32];   // 12.8 KB
    __shared__ unsigned int s_cnt[NC];      // 0.4 KB

    for (int j = threadIdx.x; j < NC * NP; j += blockDim.x) s_s[j] = 0.0f;
    for (int j = threadIdx.x; j < NC * 32; j += blockDim.x) s_q[j] = 0.0f;
    for (int j = threadIdx.x; j < NC; j += blockDim.x) s_cnt[j] = 0u;
    __syncthreads();

    const int lane = threadIdx.x & 31;
    const int gw   = (blockIdx.x * blockDim.x + threadIdx.x) >> 5;
    const int nw   = (gridDim.x * blockDim.x) >> 5;

    const int npairs = n >> 1;
    for (int k = gw; k < npairs; k += nw) {
        int r0 = k << 1;
        int r1 = r0 + 1;
        // front-batched loads (MLP)
        int   c0 = __ldg(&t[r0]);
        int   c1 = __ldg(&t[r1]);
        float a0 = __ldg(&x[(long long)r0 * NP + lane]);
        float b0 = __ldg(&x[(long long)r0 * NP + lane + 32]);
        float a1 = __ldg(&x[(long long)r1 * NP + lane]);
        float b1 = __ldg(&x[(long long)r1 * NP + lane + 32]);

        int base0 = c0 * NP + lane;
        int base1 = c1 * NP + lane;
        atomicAdd(&s_s[base0],      a0);
        atomicAdd(&s_s[base0 + 32], b0);
        atomicAdd(&s_s[base1],      a1);
        atomicAdd(&s_s[base1 + 32], b1);

        atomicAdd(&s_q[c0 * 32 + lane], a0 * a0 + b0 * b0);
        atomicAdd(&s_q[c1 * 32 + lane], a1 * a1 + b1 * b1);

        if (lane == 0) {
            atomicAdd(&s_cnt[c0], 1u);
            atomicAdd(&s_cnt[c1], 1u);
        }
    }

    // odd tail row
    if ((n & 1) && gw == 0) {
        int r = n - 1;
        int c = __ldg(&t[r]);
        float a = __ldg(&x[(long long)r * NP + lane]);
        float b = __ldg(&x[(long long)r * NP + lane + 32]);
        int base = c * NP + lane;
        atomicAdd(&s_s[base],      a);
        atomicAdd(&s_s[base + 32], b);
        atomicAdd(&s_q[c * 32 + lane], a * a + b * b);
        if (lane == 0) atomicAdd(&s_cnt[c], 1u);
    }
    __syncthreads();

    // Flush block-private accumulators to global
    for (int j = threadIdx.x; j < NC * NP; j += blockDim.x) {
        float v = s_s[j];
        if (v != 0.0f) atomicAdd(&g_s[j], v);
    }
    for (int j = threadIdx.x; j < NC * 32; j += blockDim.x) {
        float v = s_q[j];
        if (v != 0.0f) atomicAdd(&g_q[j], v);
    }
    for (int j = threadIdx.x; j < NC; j += blockDim.x) {
        unsigned cgt = s_cnt[j];
        if (cgt) atomicAdd(&g_cnt[j], cgt);
    }
}

// ---------------------------------------------------------------------------
// Kernel 3: finalize.
//   result = (1/NC) * sum_c [ (rss_c - sum_p s_cp^2 / n_c) / (n_c - 1) ]
//   where rss_c = sum_l g_q[c*32+l]
// ---------------------------------------------------------------------------
__global__ void CLIR_final_kernel(float* __restrict__ out) {
    __shared__ float red[256];
    float acc = 0.0f;

    // -sum_{c,p} s^2 / (n_c * (n_c - 1))
    for (int j = threadIdx.x; j < NC * NP; j += blockDim.x) {
        int c = j >> 6;
        float ncf = (float)g_cnt[c];
        float s = g_s[j];
        acc -= (s * s) / (ncf * (ncf - 1.0f));
    }
    // +sum_{c,l} q / (n_c - 1)
    for (int j = threadIdx.x; j < NC * 32; j += blockDim.x) {
        int c = j >> 5;
        float ncf = (float)g_cnt[c];
        acc += g_q[j] / (ncf - 1.0f);
    }

    red[threadIdx.x] = acc;
    __syncthreads();
    for (int off = 128; off > 0; off >>= 1) {
        if (threadIdx.x < off) red[threadIdx.x] += red[threadIdx.x + off];
        __syncthreads();
    }
    if (threadIdx.x == 0) out[0] = red[0] / (float)NC;
}

// ---------------------------------------------------------------------------
// Launch
// ---------------------------------------------------------------------------
extern "C" void kernel_launch(void* const* d_in, const int* in_sizes, int n_in,
                              void* d_out, int out_size) {
    const float* x = (const float*)d_in[0];
    const int*   t = (const int*)d_in[1];
    int n = in_sizes[1];

    float* out = (float*)d_out;

    CLIR_zero_kernel<<<10, 1024>>>();
    CLIR_accum_kernel<<<444, 512>>>(x, t, n);
    CLIR_final_kernel<<<1, 256>>>(out);
}

// round 6
// speedup vs baseline: 2.7297x; 1.5128x over previous
#include <cuda_runtime.h>

#define NC   100    // num classes
#define NP   64     // features per row
#define NB   592    // accumulate blocks (4 per SM x 148)
#define T    512    // threads per block
#define CAP  96     // per-class bin capacity (rows/block ~3384, mean/class ~34)

// Global scratch (device globals: allocation-free, graph-capture safe)
__device__ float        g_s[NC * NP];   // per-(class,feature) sums
__device__ float        g_rss[NC];      // per-class sum of ||x_i||^2
__device__ unsigned int g_cnt[NC];      // per-class counts

// ---------------------------------------------------------------------------
// Kernel 1: zero the global accumulators (runs every replay)
// ---------------------------------------------------------------------------
__global__ void CLIR_zero_kernel() {
    int i = blockIdx.x * blockDim.x + threadIdx.x;
    if (i < NC * NP) g_s[i] = 0.0f;
    if (i < NC) { g_rss[i] = 0.0f; g_cnt[i] = 0u; }
}

// ---------------------------------------------------------------------------
// Kernel 2: accumulate via block-local class binning.
//   Phase 1 (bin):    thread-per-row; histogram + scatter local row idx
//                     (uint16) into per-class bins. 1 shared atomic/row.
//   Phase 2 (gather): warp-per-class; rows share a class, so 64 feature
//                     sums + rss accumulate in REGISTERS (LDG.128/row,
//                     16 lanes per row, 2 rows per warp-op, 4-row unroll).
//                     One small shared flush per (warp,class).
//   Overflow (never statistically): direct atomic fallback, correctness-safe.
// ---------------------------------------------------------------------------
__global__ void __launch_bounds__(T, 4)
CLIR_accum_kernel(const float* __restrict__ x,
                  const int* __restrict__ t,
                  int n, int rpb) {
    __shared__ float          s_s[NC * NP];     // 25.6 KB
    __shared__ unsigned short s_bin[NC * CAP];  // 19.2 KB
    __shared__ unsigned int   s_cnt[NC];
    __shared__ float          s_rss[NC];

    const int tid = threadIdx.x;

    for (int j = tid; j < NC * NP; j += T) s_s[j] = 0.0f;
    for (int j = tid; j < NC; j += T) { s_cnt[j] = 0u; s_rss[j] = 0.0f; }
    __syncthreads();

    const int block_start = blockIdx.x * rpb;          // multiple of 8
    const int block_end   = min(block_start + rpb, n);
    const int nrow        = max(block_end - block_start, 0);

    // ---------------- Phase 1: bin ----------------
    {
        const int4* __restrict__ t4 = (const int4*)(t + block_start);
        const int n4 = nrow >> 2;
        for (int g = tid; g < n4; g += T) {
            int4 tc = __ldg(&t4[g]);
            int lr = g << 2;
            int cc[4] = {tc.x, tc.y, tc.z, tc.w};
            #pragma unroll
            for (int k = 0; k < 4; ++k) {
                int c = cc[k];
                unsigned p = atomicAdd(&s_cnt[c], 1u);
                if (p < CAP) {
                    s_bin[c * CAP + p] = (unsigned short)(lr + k);
                } else {
                    // statistically-never fallback: direct atomic accumulate
                    const float* row = x + (long long)(block_start + lr + k) * NP;
                    float q = 0.0f;
                    for (int f = 0; f < NP; ++f) {
                        float v = __ldg(&row[f]);
                        atomicAdd(&s_s[c * NP + f], v);
                        q += v * v;
                    }
                    atomicAdd(&s_rss[c], q);
                }
            }
        }
        for (int r = (n4 << 2) + tid; r < nrow; r += T) {
            int c = __ldg(&t[block_start + r]);
            unsigned p = atomicAdd(&s_cnt[c], 1u);
            if (p < CAP) {
                s_bin[c * CAP + p] = (unsigned short)r;
            } else {
                const float* row = x + (long long)(block_start + r) * NP;
                float q = 0.0f;
                for (int f = 0; f < NP; ++f) {
                    float v = __ldg(&row[f]);
                    atomicAdd(&s_s[c * NP + f], v);
                    q += v * v;
                }
                atomicAdd(&s_rss[c], q);
            }
        }
    }
    __syncthreads();

    // ---------------- Phase 2: gather (register accumulation) ----------------
    {
        const int wid  = tid >> 5;
        const int lane = tid & 31;
        const int l16  = lane & 15;
        const int hsel = lane >> 4;      // 0: even row of pair, 1: odd row
        const float4* __restrict__ xb =
            (const float4*)x + (long long)block_start * 16;

        for (int c = wid; c < NC; c += (T / 32)) {
            int kk = min((int)s_cnt[c], CAP);
            const unsigned short* bin = &s_bin[c * CAP];

            float s0 = 0.f, s1 = 0.f, s2 = 0.f, s3 = 0.f, q = 0.f;

            int j = 0;
            for (; j + 3 < kk; j += 4) {     // 4 rows per iter -> 2 indep LDG.128
                int liA = bin[j + hsel];
                int liB = bin[j + 2 + hsel];
                float4 a = __ldg(&xb[(long long)liA * 16 + l16]);
                float4 b = __ldg(&xb[(long long)liB * 16 + l16]);
                s0 += a.x; s1 += a.y; s2 += a.z; s3 += a.w;
                q  += a.x * a.x + a.y * a.y + a.z * a.z + a.w * a.w;
                s0 += b.x; s1 += b.y; s2 += b.z; s3 += b.w;
                q  += b.x * b.x + b.y * b.y + b.z * b.z + b.w * b.w;
            }
            for (; j < kk; j += 2) {         // predicated tail (0-3 rows)
                int jj = j + hsel;
                if (jj < kk) {
                    int li = bin[jj];
                    float4 a = __ldg(&xb[(long long)li * 16 + l16]);
                    s0 += a.x; s1 += a.y; s2 += a.z; s3 += a.w;
                    q  += a.x * a.x + a.y * a.y + a.z * a.z + a.w * a.w;
                }
            }

            if (kk) {
                int fb = c * NP + l16 * 4;   // lanes l and l+16 add same addrs (2-way)
                atomicAdd(&s_s[fb + 0], s0);
                atomicAdd(&s_s[fb + 1], s1);
                atomicAdd(&s_s[fb + 2], s2);
                atomicAdd(&s_s[fb + 3], s3);
                q += __shfl_xor_sync(0xffffffffu, q, 16);
                q += __shfl_xor_sync(0xffffffffu, q, 8);
                q += __shfl_xor_sync(0xffffffffu, q, 4);
                q += __shfl_xor_sync(0xffffffffu, q, 2);
                q += __shfl_xor_sync(0xffffffffu, q, 1);
                if (lane == 0) atomicAdd(&s_rss[c], q);
            }
        }
    }
    __syncthreads();

    // ---------------- Flush block accumulators to global ----------------
    for (int j = tid; j < NC * NP; j += T) {
        float v = s_s[j];
        if (v != 0.0f) atomicAdd(&g_s[j], v);
    }
    for (int j = tid; j < NC; j += T) {
        float r = s_rss[j];
        if (r != 0.0f) atomicAdd(&g_rss[j], r);
        unsigned cgt = s_cnt[j];
        if (cgt) atomicAdd(&g_cnt[j], cgt);
    }
}

// ---------------------------------------------------------------------------
// Kernel 3: finalize.
//   result = (1/NC) * sum_c [ (rss_c - sum_p s_cp^2 / n_c) / (n_c - 1) ]
// ---------------------------------------------------------------------------
__global__ void CLIR_final_kernel(float* __restrict__ out) {
    __shared__ float red[256];
    float acc = 0.0f;

    for (int j = threadIdx.x; j < NC * NP; j += blockDim.x) {
        int c = j >> 6;
        float ncf = (float)g_cnt[c];
        float s = g_s[j];
        acc -= (s * s) / (ncf * (ncf - 1.0f));
    }
    for (int c = threadIdx.x; c < NC; c += blockDim.x) {
        float ncf = (float)g_cnt[c];
        acc += g_rss[c] / (ncf - 1.0f);
    }

    red[threadIdx.x] = acc;
    __syncthreads();
    for (int off = 128; off > 0; off >>= 1) {
        if (threadIdx.x < off) red[threadIdx.x] += red[threadIdx.x + off];
        __syncthreads();
    }
    if (threadIdx.x == 0) out[0] = red[0] / (float)NC;
}

// ---------------------------------------------------------------------------
// Launch
// ---------------------------------------------------------------------------
extern "C" void kernel_launch(void* const* d_in, const int* in_sizes, int n_in,
                              void* d_out, int out_size) {
    const float* x = (const float*)d_in[0];
    const int*   t = (const int*)d_in[1];
    int n = in_sizes[1];

    float* out = (float*)d_out;

    int rpb = (((n + NB - 1) / NB) + 7) & ~7;   // rows per block, multiple of 8

    CLIR_zero_kernel<<<7, 1024>>>();
    CLIR_accum_kernel<<<NB, T>>>(x, t, n, rpb);
    CLIR_final_kernel<<<1, 256>>>(out);
}